// round 16
// baseline (speedup 1.0000x reference)
#include <cuda_runtime.h>
#include <cuda_bf16.h>
#include <cstdint>

#define Nn   50000
#define NPAD 50048
#define Ee   800000
#define DIN  128
#define DH   256
#define DOUT 128
#define BNEPS 1e-5f
#define SCANB 196          // ceil(Nn/256)

// ---------------- scratch (device globals: allocation-free) ----------------
__device__ int   g_is64;
__device__ __align__(256) int    g_src [Ee];
__device__ __align__(256) int    g_dst [Ee];
__device__ __align__(256) float2 g_nb  [Ee];     // packed (src as int bits, nrm)
__device__ __align__(256) int    g_rowptr[Nn + 1];
__device__ __align__(256) int    g_cursor[Nn];
__device__ __align__(256) int    g_cnt [Nn];
__device__ __align__(256) int    g_blksum[SCANB];
__device__ __align__(256) float  g_dinv[Nn];
__device__ __align__(256) float  g_bufA[(size_t)Nn * DH];
__device__ __align__(256) float  g_bufB[(size_t)Nn * DH];
__device__ __align__(256) float  g_bufC[(size_t)Nn * DH];
__device__ __align__(256) __nv_bfloat16 g_W0s[(size_t)2 * DIN * DH];
__device__ __align__(256) __nv_bfloat16 g_W1s[(size_t)2 * DH * DH];
__device__ __align__(256) __nv_bfloat16 g_W2s[(size_t)2 * DH * DOUT];
__device__ __align__(256) float g_sum0  [DH];
__device__ __align__(256) float g_sumsq0[DH];
__device__ __align__(256) float g_sum1  [DH];
__device__ __align__(256) float g_sumsq1[DH];

__device__ __forceinline__ uint32_t smem_u32(const void* p) {
    uint32_t a;
    asm("{ .reg .u64 t; cvta.to.shared.u64 t, %1; cvt.u32.u64 %0, t; }" : "=r"(a) : "l"(p));
    return a;
}

#define MMA16816(d, a, b)                                                     \
    asm volatile("mma.sync.aligned.m16n8k16.row.col.f32.bf16.bf16.f32 "       \
                 "{%0,%1,%2,%3}, {%4,%5,%6,%7}, {%8,%9}, {%0,%1,%2,%3};"      \
                 : "+f"((d)[0]), "+f"((d)[1]), "+f"((d)[2]), "+f"((d)[3])     \
                 : "r"((a)[0]), "r"((a)[1]), "r"((a)[2]), "r"((a)[3]),        \
                   "r"((b)[0]), "r"((b)[1]))

#define LDSM_X4(f, addr)                                                          \
    asm volatile("ldmatrix.sync.aligned.m8n8.x4.shared.b16 {%0,%1,%2,%3}, [%4];"  \
                 : "=r"((f)[0]), "=r"((f)[1]), "=r"((f)[2]), "=r"((f)[3]) : "r"(addr))

#define LDSM_X2(f, addr)                                                      \
    asm volatile("ldmatrix.sync.aligned.m8n8.x2.shared.b16 {%0,%1}, [%2];"    \
                 : "=r"((f)[0]), "=r"((f)[1]) : "r"(addr))

__device__ __forceinline__ float4 bnrelu4(float4 t, float4 sc, float4 sh) {
    t.x = fmaxf(fmaf(t.x, sc.x, sh.x), 0.0f);
    t.y = fmaxf(fmaf(t.y, sc.y, sh.y), 0.0f);
    t.z = fmaxf(fmaf(t.z, sc.z, sh.z), 0.0f);
    t.w = fmaxf(fmaf(t.w, sc.w, sh.w), 0.0f);
    return t;
}
__device__ __forceinline__ void fma4(float4& a, float4 t, float w) {
    a.x = fmaf(t.x, w, a.x); a.y = fmaf(t.y, w, a.y);
    a.z = fmaf(t.z, w, a.z); a.w = fmaf(t.w, w, a.w);
}

// compute BN scale/shift (float4 of columns c..c+3) from sums + gamma/beta
__device__ __forceinline__ void bn_params4(
    const float* __restrict__ sum, const float* __restrict__ sumsq,
    const float* __restrict__ g, const float* __restrict__ be,
    int c4, float4& sc, float4& sh) {
    float4 su = ((const float4*)sum)[c4];
    float4 sq = ((const float4*)sumsq)[c4];
    float4 gg = ((const float4*)g)[c4];
    float4 bb = ((const float4*)be)[c4];
    const float inv = 1.0f / Nn;
    float mu, var;
    mu = su.x * inv; var = sq.x * inv - mu * mu;
    sc.x = gg.x * rsqrtf(var + BNEPS); sh.x = bb.x - mu * sc.x;
    mu = su.y * inv; var = sq.y * inv - mu * mu;
    sc.y = gg.y * rsqrtf(var + BNEPS); sh.y = bb.y - mu * sc.y;
    mu = su.z * inv; var = sq.z * inv - mu * mu;
    sc.z = gg.z * rsqrtf(var + BNEPS); sh.z = bb.z - mu * sc.z;
    mu = su.w * inv; var = sq.w * inv - mu * mu;
    sc.w = gg.w * rsqrtf(var + BNEPS); sh.w = bb.w - mu * sc.w;
}

// ---------------- detect dtype + zero counters & BN sums ----------------
__global__ void k_detect_zero(const uint2* __restrict__ ei) {
    int i = blockIdx.x * blockDim.x + threadIdx.x;
    if (i < Nn) g_cnt[i] = 0;
    if (i < DH) {
        g_sum0[i] = 0.0f; g_sumsq0[i] = 0.0f;
        g_sum1[i] = 0.0f; g_sumsq1[i] = 0.0f;
    }
    if (i == 0) {
        int is64 = 1;
        for (int j = 0; j < 64; j++)
            if (ei[j].y != 0u) { is64 = 0; break; }
        g_is64 = is64;
    }
}

// convert + fused degree count
__global__ void k_convert(const void* __restrict__ ei) {
    int e = blockIdx.x * blockDim.x + threadIdx.x;
    if (e >= Ee) return;
    int s, d;
    if (g_is64) {
        const long long* p = (const long long*)ei;
        s = (int)p[e];
        d = (int)p[e + Ee];
    } else {
        const int* p = (const int*)ei;
        s = p[e];
        d = p[e + Ee];
    }
    s = min(max(s, 0), Nn - 1);
    d = min(max(d, 0), Nn - 1);
    g_src[e] = s;
    g_dst[e] = d;
    atomicAdd(&g_cnt[d], 1);
}

// ---------------- 2-phase scan over g_cnt -------------------------
__global__ void k_scan1() {
    __shared__ int sh[256];
    int i = blockIdx.x * 256 + threadIdx.x;
    int v = (i < Nn) ? g_cnt[i] : 0;
    sh[threadIdx.x] = v;
    __syncthreads();
#pragma unroll
    for (int off = 128; off > 0; off >>= 1) {
        if (threadIdx.x < off) sh[threadIdx.x] += sh[threadIdx.x + off];
        __syncthreads();
    }
    if (threadIdx.x == 0) g_blksum[blockIdx.x] = sh[0];
}

// scan3: each block redundantly scans blksum (196 ints) then local scan
__global__ void k_scan3() {
    __shared__ int shb[256];
    __shared__ int sh[256];
    int t = threadIdx.x;
    int bv = (t < SCANB) ? g_blksum[t] : 0;
    shb[t] = bv;
    __syncthreads();
#pragma unroll
    for (int off = 1; off < 256; off <<= 1) {
        int u = (t >= off) ? shb[t - off] : 0;
        __syncthreads();
        shb[t] += u;
        __syncthreads();
    }
    int blkoff = shb[blockIdx.x] - g_blksum[blockIdx.x];   // exclusive prefix

    int i = blockIdx.x * 256 + t;
    int c = (i < Nn) ? g_cnt[i] : 0;
    sh[t] = c;
    __syncthreads();
#pragma unroll
    for (int off = 1; off < 256; off <<= 1) {
        int u = (t >= off) ? sh[t - off] : 0;
        __syncthreads();
        sh[t] += u;
        __syncthreads();
    }
    if (i < Nn) {
        int pre = blkoff + sh[t] - c;
        g_rowptr[i] = pre;
        g_cursor[i] = pre;
        g_dinv[i]   = rsqrtf((float)(c + 1));
    }
    if (i == Nn - 1) g_rowptr[Nn] = Ee;
}

__global__ void k_fill() {
    int e = blockIdx.x * blockDim.x + threadIdx.x;
    if (e >= Ee) return;
    int s = g_src[e];
    int d = g_dst[e];
    int pos = atomicAdd(&g_cursor[d], 1);
    g_nb[pos] = make_float2(__int_as_float(s), g_dinv[s] * g_dinv[d]);
}

// ---------------- gather aggregation: one warp per node --------------------
// MODE 0: out[n] = dinv2*in[n] + sum w*in[s]
// MODE 1: same but every read is relu(bn0(.)); bn params computed inline
// MODE 2: out[n] = dinv2*in[n] + x[n] + b2 + sum w*in[s]
// Packed (src,nrm) descriptors, software-prefetched one 4-edge group ahead.
template<int F, int MODE>
__global__ void __launch_bounds__(256)
k_gather(const float* __restrict__ in, const float* __restrict__ xres,
         const float* __restrict__ b2,
         const float* __restrict__ gam, const float* __restrict__ bet,
         float* __restrict__ out) {
    int n = (blockIdx.x * blockDim.x + threadIdx.x) >> 5;
    if (n >= Nn) return;
    int lane = threadIdx.x & 31;
    constexpr int V = F / 128;

    float4 sc[V], sh[V];
    if (MODE == 1) {
#pragma unroll
        for (int v = 0; v < V; v++)
            bn_params4(g_sum0, g_sumsq0, gam, bet, lane + 32 * v, sc[v], sh[v]);
    }
    float di = g_dinv[n], s2 = di * di;
    float4 acc[V];
    {
        const float4* rn = (const float4*)(in + (size_t)n * F);
#pragma unroll
        for (int v = 0; v < V; v++) {
            float4 t = __ldg(&rn[lane + 32 * v]);
            if (MODE == 1) t = bnrelu4(t, sc[v], sh[v]);
            acc[v] = make_float4(t.x * s2, t.y * s2, t.z * s2, t.w * s2);
        }
    }
    if (MODE == 2) {
        const float4* xr = (const float4*)(xres + (size_t)n * F);
#pragma unroll
        for (int v = 0; v < V; v++) {
            float4 xx = __ldg(&xr[lane + 32 * v]);
            float4 bb = __ldg(&((const float4*)b2)[lane + 32 * v]);
            acc[v].x += xx.x + bb.x;
            acc[v].y += xx.y + bb.y;
            acc[v].z += xx.z + bb.z;
            acc[v].w += xx.w + bb.w;
        }
    }

    int e   = g_rowptr[n];
    int end = g_rowptr[n + 1];
    int ngrp = (end - e) >> 2;

    float2 c0, c1, c2, c3;
    if (ngrp > 0) {
        c0 = __ldg(&g_nb[e]);
        c1 = __ldg(&g_nb[e + 1]);
        c2 = __ldg(&g_nb[e + 2]);
        c3 = __ldg(&g_nb[e + 3]);
    }
    for (int g = 0; g < ngrp; g++) {
        float2 n0, n1, n2, n3;
        if (g + 1 < ngrp) {                  // prefetch next group's descriptors
            int nb = e + (g + 1) * 4;
            n0 = __ldg(&g_nb[nb]);
            n1 = __ldg(&g_nb[nb + 1]);
            n2 = __ldg(&g_nb[nb + 2]);
            n3 = __ldg(&g_nb[nb + 3]);
        }
        int i0 = __float_as_int(c0.x), i1 = __float_as_int(c1.x);
        int i2 = __float_as_int(c2.x), i3 = __float_as_int(c3.x);
        const float4* r0 = (const float4*)(in + (size_t)i0 * F) + lane;
        const float4* r1 = (const float4*)(in + (size_t)i1 * F) + lane;
        const float4* r2 = (const float4*)(in + (size_t)i2 * F) + lane;
        const float4* r3 = (const float4*)(in + (size_t)i3 * F) + lane;
#pragma unroll
        for (int v = 0; v < V; v++) {
            float4 t0 = __ldg(r0 + 32 * v);
            float4 t1 = __ldg(r1 + 32 * v);
            float4 t2 = __ldg(r2 + 32 * v);
            float4 t3 = __ldg(r3 + 32 * v);
            if (MODE == 1) {
                t0 = bnrelu4(t0, sc[v], sh[v]);
                t1 = bnrelu4(t1, sc[v], sh[v]);
                t2 = bnrelu4(t2, sc[v], sh[v]);
                t3 = bnrelu4(t3, sc[v], sh[v]);
            }
            fma4(acc[v], t0, c0.y);
            fma4(acc[v], t1, c1.y);
            fma4(acc[v], t2, c2.y);
            fma4(acc[v], t3, c3.y);
        }
        c0 = n0; c1 = n1; c2 = n2; c3 = n3;
    }
    for (e += ngrp * 4; e < end; e++) {
        float2 p = __ldg(&g_nb[e]);
        int   s = __float_as_int(p.x);
        const float4* r = (const float4*)(in + (size_t)s * F) + lane;
#pragma unroll
        for (int v = 0; v < V; v++) {
            float4 t = __ldg(r + 32 * v);
            if (MODE == 1) t = bnrelu4(t, sc[v], sh[v]);
            fma4(acc[v], t, p.y);
        }
    }

    float4* o = (float4*)(out + (size_t)n * F);
#pragma unroll
    for (int v = 0; v < V; v++) __stcs(&o[lane + 32 * v], acc[v]);
}

// ---------------- all 3 weight splits in ONE kernel -------------------------
__global__ void k_cvtB_all(const float* __restrict__ W0, const float* __restrict__ W1,
                           const float* __restrict__ W2) {
    int idx = blockIdx.x * blockDim.x + threadIdx.x;
    const float* W; __nv_bfloat16* out; int K, Nc, loc;
    if (idx < 32768)       { W = W0; out = g_W0s; K = DIN; Nc = DH;   loc = idx; }
    else if (idx < 98304)  { W = W1; out = g_W1s; K = DH;  Nc = DH;   loc = idx - 32768; }
    else if (idx < 131072) { W = W2; out = g_W2s; K = DH;  Nc = DOUT; loc = idx - 98304; }
    else return;
    int k = loc / Nc, n = loc - k * Nc;
    float v = W[loc];
    __nv_bfloat16 h = __float2bfloat16(v);
    __nv_bfloat16 l = __float2bfloat16(v - __bfloat162float(h));
    out[(size_t)n * K + k]                  = h;
    out[(size_t)Nc * K + (size_t)n * K + k] = l;
}

// ---------------- fused-split mma.sync GEMM (40KB static smem, 2 CTAs/SM,
// register double-buffer). FUSE: A = relu(bn1(A)) + relu(bn0(A0)), inline BN.
#define LDPE 40
#define GEMM_PREFETCH(kc)                                                         \
    {                                                                             \
        _Pragma("unroll")                                                         \
        for (int it = 0; it < 4; it++) {                                          \
            int u = tid + it * 256, r = u >> 3, c4 = u & 7;                       \
            int gr = brow + r;                                                    \
            if (gr < Nn) {                                                        \
                pa[it] = *(const float4*)(A + (size_t)gr * K + (kc) + c4 * 4);    \
                if (FUSE)                                                         \
                    pa0[it] = *(const float4*)(A0 + (size_t)gr * K + (kc) + c4 * 4);\
            } else {                                                              \
                pa[it] = make_float4(0.f, 0.f, 0.f, 0.f);                         \
                if (FUSE) pa0[it] = make_float4(0.f, 0.f, 0.f, 0.f);              \
            }                                                                     \
        }                                                                         \
        _Pragma("unroll")                                                         \
        for (int it = 0; it < 2; it++) {                                          \
            int u = tid + it * 256, r = u >> 2, c8 = u & 3;                       \
            const __nv_bfloat16* bp = B2 + (size_t)(bcol + r) * K + (kc) + c8 * 8;\
            pbh[it] = *(const uint4*)bp;                                          \
            pbl[it] = *(const uint4*)(bp + (size_t)NcT * K);                      \
        }                                                                         \
    }

#define GEMM_COMMIT(kc)                                                           \
    {                                                                             \
        float4 s1v, t1v, s0v, t0v;                                                \
        if (FUSE) {                                                               \
            int cb = ((kc) >> 2) + (tid & 7);                                     \
            bn_params4(g_sum1, g_sumsq1, gam1, bet1, cb, s1v, t1v);               \
            bn_params4(g_sum0, g_sumsq0, gam0, bet0, cb, s0v, t0v);               \
        }                                                                         \
        _Pragma("unroll")                                                         \
        for (int it = 0; it < 4; it++) {                                          \
            int u = tid + it * 256, r = u >> 3, c4 = u & 7;                       \
            float4 v4 = pa[it];                                                   \
            if (FUSE) {                                                           \
                v4 = bnrelu4(v4, s1v, t1v);                                       \
                float4 w4 = bnrelu4(pa0[it], s0v, t0v);                           \
                v4.x += w4.x; v4.y += w4.y; v4.z += w4.z; v4.w += w4.w;           \
            }                                                                     \
            float vv[4] = {v4.x, v4.y, v4.z, v4.w};                               \
            __nv_bfloat16 hh[4], ll[4];                                           \
            _Pragma("unroll")                                                     \
            for (int q = 0; q < 4; q++) {                                         \
                hh[q] = __float2bfloat16(vv[q]);                                  \
                ll[q] = __float2bfloat16(vv[q] - __bfloat162float(hh[q]));        \
            }                                                                     \
            *(uint2*)&sAh[r][c4 * 4] = *(uint2*)hh;                               \
            *(uint2*)&sAl[r][c4 * 4] = *(uint2*)ll;                               \
        }                                                                         \
        _Pragma("unroll")                                                         \
        for (int it = 0; it < 2; it++) {                                          \
            int u = tid + it * 256, r = u >> 2, c8 = u & 3;                       \
            *(uint4*)&sBh[r][c8 * 8] = pbh[it];                                   \
            *(uint4*)&sBl[r][c8 * 8] = pbl[it];                                   \
        }                                                                         \
    }

template<int K, bool STATS, bool FUSE>
__global__ void __launch_bounds__(256)
k_gemmF(const float* __restrict__ A, const float* __restrict__ A0,
        const __nv_bfloat16* __restrict__ B2,
        float* __restrict__ C, int NcT,
        float* __restrict__ sumP, float* __restrict__ sumsqP,
        const float* __restrict__ gam0, const float* __restrict__ bet0,
        const float* __restrict__ gam1, const float* __restrict__ bet1) {
    __shared__ __align__(16) __nv_bfloat16 sAh[128][LDPE];
    __shared__ __align__(16) __nv_bfloat16 sAl[128][LDPE];
    __shared__ __align__(16) __nv_bfloat16 sBh[128][LDPE];
    __shared__ __align__(16) __nv_bfloat16 sBl[128][LDPE];

    int tid  = threadIdx.x;
    int wid  = tid >> 5;
    int lane = tid & 31;
    int brow = blockIdx.y * 128;
    int bcol = blockIdx.x * 128;

    int warp_m = wid >> 2;
    int warp_n = wid & 3;
    int m_base = warp_m * 64;
    int n_base = warp_n * 32;

    float acc[4][4][4];
#pragma unroll
    for (int i = 0; i < 4; i++)
#pragma unroll
        for (int j = 0; j < 4; j++)
#pragma unroll
            for (int q = 0; q < 4; q++) acc[i][j][q] = 0.0f;

    float4 pa[4], pa0[4];
    uint4  pbh[2], pbl[2];

    GEMM_PREFETCH(0);
    constexpr int NCH = K / 32;
    for (int c = 0; c < NCH; c++) {
        GEMM_COMMIT(c * 32);
        __syncthreads();
        if (c + 1 < NCH) GEMM_PREFETCH((c + 1) * 32);

#pragma unroll
        for (int ks = 0; ks < 2; ks++) {
            uint32_t ah[4][4], al[4][4];
#pragma unroll
            for (int i = 0; i < 4; i++) {
                int rr = m_base + i * 16 + (lane & 15);
                int cc = ks * 16 + (lane >> 4) * 8;
                uint32_t ad = smem_u32(&sAh[rr][cc]);
                LDSM_X4(ah[i], ad);
                ad = smem_u32(&sAl[rr][cc]);
                LDSM_X4(al[i], ad);
            }
#pragma unroll
            for (int j = 0; j < 4; j++) {
                int rr = n_base + j * 8 + (lane & 7);
                int cc = ks * 16 + ((lane >> 3) & 1) * 8;
                uint32_t bh2[2], bl2[2];
                uint32_t bd = smem_u32(&sBh[rr][cc]);
                LDSM_X2(bh2, bd);
                bd = smem_u32(&sBl[rr][cc]);
                LDSM_X2(bl2, bd);
#pragma unroll
                for (int i = 0; i < 4; i++) {
                    MMA16816(acc[i][j], ah[i], bh2);
                    MMA16816(acc[i][j], al[i], bh2);
                    MMA16816(acc[i][j], ah[i], bl2);
                }
            }
        }
        __syncthreads();
    }

    // write C (streaming: written once, read once later)
#pragma unroll
    for (int i = 0; i < 4; i++) {
        int row0 = brow + m_base + i * 16 + (lane >> 2);
        int row1 = row0 + 8;
#pragma unroll
        for (int j = 0; j < 4; j++) {
            int col = bcol + n_base + j * 8 + (lane & 3) * 2;
            if (row0 < Nn)
                __stcs((float2*)(C + (size_t)row0 * NcT + col),
                       make_float2(acc[i][j][0], acc[i][j][1]));
            if (row1 < Nn)
                __stcs((float2*)(C + (size_t)row1 * NcT + col),
                       make_float2(acc[i][j][2], acc[i][j][3]));
        }
    }

    // fused BN column stats
    if (STATS) {
#pragma unroll
        for (int j = 0; j < 4; j++) {
            float s0 = 0.f, q0 = 0.f, s1 = 0.f, q1 = 0.f;
#pragma unroll
            for (int i = 0; i < 4; i++) {
                int r0 = brow + m_base + i * 16 + (lane >> 2);
                int r1 = r0 + 8;
                float v00 = (r0 < Nn) ? acc[i][j][0] : 0.f;
                float v01 = (r0 < Nn) ? acc[i][j][1] : 0.f;
                float v10 = (r1 < Nn) ? acc[i][j][2] : 0.f;
                float v11 = (r1 < Nn) ? acc[i][j][3] : 0.f;
                s0 += v00 + v10; q0 += v00 * v00 + v10 * v10;
                s1 += v01 + v11; q1 += v01 * v01 + v11 * v11;
            }
#pragma unroll
            for (int m = 4; m <= 16; m <<= 1) {
                s0 += __shfl_xor_sync(0xFFFFFFFFu, s0, m);
                q0 += __shfl_xor_sync(0xFFFFFFFFu, q0, m);
                s1 += __shfl_xor_sync(0xFFFFFFFFu, s1, m);
                q1 += __shfl_xor_sync(0xFFFFFFFFu, q1, m);
            }
            if (lane < 4) {
                int col = bcol + n_base + j * 8 + lane * 2;
                atomicAdd(&sumP[col],       s0);
                atomicAdd(&sumsqP[col],     q0);
                atomicAdd(&sumP[col + 1],   s1);
                atomicAdd(&sumsqP[col + 1], q1);
            }
        }
    }
}

// ---------------- launch ----------------
extern "C" void kernel_launch(void* const* d_in, const int* in_sizes, int n_in,
                              void* d_out, int out_size) {
    const float* x  = (const float*)d_in[0];
    const void*  ei = d_in[1];
    const float* W0 = (const float*)d_in[2];
    // b0 = d_in[3]  (cancels exactly through BatchNorm)
    const float* g0  = (const float*)d_in[4];
    const float* be0 = (const float*)d_in[5];
    const float* W1  = (const float*)d_in[6];
    // b1 = d_in[7]  (cancels exactly through BatchNorm)
    const float* g1  = (const float*)d_in[8];
    const float* be1 = (const float*)d_in[9];
    const float* W2  = (const float*)d_in[10];
    const float* b2  = (const float*)d_in[11];
    float* out = (float*)d_out;

    float *bufA, *bufB, *bufC;
    __nv_bfloat16 *W0s, *W1s, *W2s;
    float *sum0, *sumsq0, *sum1, *sumsq1;
    cudaGetSymbolAddress((void**)&bufA, g_bufA);
    cudaGetSymbolAddress((void**)&bufB, g_bufB);
    cudaGetSymbolAddress((void**)&bufC, g_bufC);
    cudaGetSymbolAddress((void**)&W0s,  g_W0s);
    cudaGetSymbolAddress((void**)&W1s,  g_W1s);
    cudaGetSymbolAddress((void**)&W2s,  g_W2s);
    cudaGetSymbolAddress((void**)&sum0,   g_sum0);
    cudaGetSymbolAddress((void**)&sumsq0, g_sumsq0);
    cudaGetSymbolAddress((void**)&sum1,   g_sum1);
    cudaGetSymbolAddress((void**)&sumsq1, g_sumsq1);

    const int TB = 256;
    int gridE1 = (Ee + TB - 1) / TB;
    int gridN1 = (Nn + TB - 1) / TB;
    int gridW  = (Nn * 32 + TB - 1) / TB;    // 1 warp / node
    dim3 gemmG2(2, NPAD / 128);   // Nc=256
    dim3 gemmG1(1, NPAD / 128);   // Nc=128

    // setup
    k_detect_zero<<<gridN1, TB>>>((const uint2*)ei);
    k_convert<<<gridE1, TB>>>(ei);
    k_scan1  <<<SCANB, 256>>>();
    k_scan3  <<<SCANB, 256>>>();
    k_fill   <<<gridE1, TB>>>();
    k_cvtB_all<<<(131072 + TB - 1) / TB, TB>>>(W0, W1, W2);

    // ---- layer 0 ----
    k_gather<DIN, 0><<<gridW, TB>>>(x, nullptr, nullptr, nullptr, nullptr, bufA);
    k_gemmF<DIN, true, false><<<gemmG2, 256>>>(bufA, nullptr, W0s, bufB, DH,
                                               sum0, sumsq0,
                                               nullptr, nullptr, nullptr, nullptr); // H0

    // ---- layer 1: gather applies relu(bn0(.)) with inline BN params ----
    k_gather<DH, 1><<<gridW, TB>>>(bufB, nullptr, nullptr, g0, be0, bufC);
    k_gemmF<DH, true, false><<<gemmG2, 256>>>(bufC, nullptr, W1s, bufA, DH,
                                              sum1, sumsq1,
                                              nullptr, nullptr, nullptr, nullptr);  // M1

    // ---- layer 2: h2 computed in-GEMM from M1(bufA) + H0(bufB), inline BN ----
    k_gemmF<DH, false, true><<<gemmG1, 256>>>(bufA, bufB, W2s, bufC, DOUT,
                                              nullptr, nullptr,
                                              g0, be0, g1, be1);                    // M2
    k_gather<DOUT, 2><<<gridW, TB>>>(bufC, x, b2, nullptr, nullptr, out);
}

// round 17
// speedup vs baseline: 1.0660x; 1.0660x over previous
#include <cuda_runtime.h>
#include <cuda_bf16.h>
#include <cstdint>

#define Nn   50000
#define NPAD 50048
#define Ee   800000
#define DIN  128
#define DH   256
#define DOUT 128
#define BNEPS 1e-5f
#define SCANB 196          // ceil(Nn/256)

// ---------------- scratch (device globals: allocation-free) ----------------
__device__ int   g_is64;
__device__ __align__(256) int   g_src [Ee];
__device__ __align__(256) int   g_dst [Ee];
__device__ __align__(256) int   g_nb_src[Ee];
__device__ __align__(256) float g_nb_nrm[Ee];
__device__ __align__(256) int   g_rowptr[Nn + 1];
__device__ __align__(256) int   g_cursor[Nn];
__device__ __align__(256) int   g_cnt [Nn];
__device__ __align__(256) int   g_blksum[SCANB];
__device__ __align__(256) float g_dinv[Nn];
__device__ __align__(256) float g_bufA[(size_t)Nn * DH];
__device__ __align__(256) float g_bufB[(size_t)Nn * DH];
__device__ __align__(256) float g_bufC[(size_t)Nn * DH];
__device__ __align__(256) __nv_bfloat16 g_W0s[(size_t)2 * DIN * DH];
__device__ __align__(256) __nv_bfloat16 g_W1s[(size_t)2 * DH * DH];
__device__ __align__(256) __nv_bfloat16 g_W2s[(size_t)2 * DH * DOUT];
__device__ __align__(256) float g_sum0  [DH];
__device__ __align__(256) float g_sumsq0[DH];
__device__ __align__(256) float g_sum1  [DH];
__device__ __align__(256) float g_sumsq1[DH];

__device__ __forceinline__ uint32_t smem_u32(const void* p) {
    uint32_t a;
    asm("{ .reg .u64 t; cvta.to.shared.u64 t, %1; cvt.u32.u64 %0, t; }" : "=r"(a) : "l"(p));
    return a;
}

#define MMA16816(d, a, b)                                                     \
    asm volatile("mma.sync.aligned.m16n8k16.row.col.f32.bf16.bf16.f32 "       \
                 "{%0,%1,%2,%3}, {%4,%5,%6,%7}, {%8,%9}, {%0,%1,%2,%3};"      \
                 : "+f"((d)[0]), "+f"((d)[1]), "+f"((d)[2]), "+f"((d)[3])     \
                 : "r"((a)[0]), "r"((a)[1]), "r"((a)[2]), "r"((a)[3]),        \
                   "r"((b)[0]), "r"((b)[1]))

#define LDSM_X4(f, addr)                                                          \
    asm volatile("ldmatrix.sync.aligned.m8n8.x4.shared.b16 {%0,%1,%2,%3}, [%4];"  \
                 : "=r"((f)[0]), "=r"((f)[1]), "=r"((f)[2]), "=r"((f)[3]) : "r"(addr))

#define LDSM_X2(f, addr)                                                      \
    asm volatile("ldmatrix.sync.aligned.m8n8.x2.shared.b16 {%0,%1}, [%2];"    \
                 : "=r"((f)[0]), "=r"((f)[1]) : "r"(addr))

__device__ __forceinline__ float4 bnrelu4(float4 t, float4 sc, float4 sh) {
    t.x = fmaxf(fmaf(t.x, sc.x, sh.x), 0.0f);
    t.y = fmaxf(fmaf(t.y, sc.y, sh.y), 0.0f);
    t.z = fmaxf(fmaf(t.z, sc.z, sh.z), 0.0f);
    t.w = fmaxf(fmaf(t.w, sc.w, sh.w), 0.0f);
    return t;
}
__device__ __forceinline__ void fma4(float4& a, float4 t, float w) {
    a.x = fmaf(t.x, w, a.x); a.y = fmaf(t.y, w, a.y);
    a.z = fmaf(t.z, w, a.z); a.w = fmaf(t.w, w, a.w);
}

// compute BN scale/shift (float4 of columns c..c+3) from sums + gamma/beta
__device__ __forceinline__ void bn_params4(
    const float* __restrict__ sum, const float* __restrict__ sumsq,
    const float* __restrict__ g, const float* __restrict__ be,
    int c4, float4& sc, float4& sh) {
    float4 su = ((const float4*)sum)[c4];
    float4 sq = ((const float4*)sumsq)[c4];
    float4 gg = ((const float4*)g)[c4];
    float4 bb = ((const float4*)be)[c4];
    const float inv = 1.0f / Nn;
    float mu, var;
    mu = su.x * inv; var = sq.x * inv - mu * mu;
    sc.x = gg.x * rsqrtf(var + BNEPS); sh.x = bb.x - mu * sc.x;
    mu = su.y * inv; var = sq.y * inv - mu * mu;
    sc.y = gg.y * rsqrtf(var + BNEPS); sh.y = bb.y - mu * sc.y;
    mu = su.z * inv; var = sq.z * inv - mu * mu;
    sc.z = gg.z * rsqrtf(var + BNEPS); sh.z = bb.z - mu * sc.z;
    mu = su.w * inv; var = sq.w * inv - mu * mu;
    sc.w = gg.w * rsqrtf(var + BNEPS); sh.w = bb.w - mu * sc.w;
}

// ---------------- detect dtype + zero counters & BN sums ----------------
__global__ void k_detect_zero(const uint2* __restrict__ ei) {
    int i = blockIdx.x * blockDim.x + threadIdx.x;
    if (i < Nn) g_cnt[i] = 0;
    if (i < DH) {
        g_sum0[i] = 0.0f; g_sumsq0[i] = 0.0f;
        g_sum1[i] = 0.0f; g_sumsq1[i] = 0.0f;
    }
    if (i == 0) {
        int is64 = 1;
        for (int j = 0; j < 64; j++)
            if (ei[j].y != 0u) { is64 = 0; break; }
        g_is64 = is64;
    }
}

// convert + fused degree count
__global__ void k_convert(const void* __restrict__ ei) {
    int e = blockIdx.x * blockDim.x + threadIdx.x;
    if (e >= Ee) return;
    int s, d;
    if (g_is64) {
        const long long* p = (const long long*)ei;
        s = (int)p[e];
        d = (int)p[e + Ee];
    } else {
        const int* p = (const int*)ei;
        s = p[e];
        d = p[e + Ee];
    }
    s = min(max(s, 0), Nn - 1);
    d = min(max(d, 0), Nn - 1);
    g_src[e] = s;
    g_dst[e] = d;
    atomicAdd(&g_cnt[d], 1);
}

// ---------------- 2-phase scan over g_cnt -------------------------
__global__ void k_scan1() {
    __shared__ int sh[256];
    int i = blockIdx.x * 256 + threadIdx.x;
    int v = (i < Nn) ? g_cnt[i] : 0;
    sh[threadIdx.x] = v;
    __syncthreads();
#pragma unroll
    for (int off = 128; off > 0; off >>= 1) {
        if (threadIdx.x < off) sh[threadIdx.x] += sh[threadIdx.x + off];
        __syncthreads();
    }
    if (threadIdx.x == 0) g_blksum[blockIdx.x] = sh[0];
}

// scan3: each block redundantly scans blksum (196 ints) then local scan
__global__ void k_scan3() {
    __shared__ int shb[256];
    __shared__ int sh[256];
    int t = threadIdx.x;
    int bv = (t < SCANB) ? g_blksum[t] : 0;
    shb[t] = bv;
    __syncthreads();
#pragma unroll
    for (int off = 1; off < 256; off <<= 1) {
        int u = (t >= off) ? shb[t - off] : 0;
        __syncthreads();
        shb[t] += u;
        __syncthreads();
    }
    int blkoff = shb[blockIdx.x] - g_blksum[blockIdx.x];   // exclusive prefix

    int i = blockIdx.x * 256 + t;
    int c = (i < Nn) ? g_cnt[i] : 0;
    sh[t] = c;
    __syncthreads();
#pragma unroll
    for (int off = 1; off < 256; off <<= 1) {
        int u = (t >= off) ? sh[t - off] : 0;
        __syncthreads();
        sh[t] += u;
        __syncthreads();
    }
    if (i < Nn) {
        int pre = blkoff + sh[t] - c;
        g_rowptr[i] = pre;
        g_cursor[i] = pre;
        g_dinv[i]   = rsqrtf((float)(c + 1));
    }
    if (i == Nn - 1) g_rowptr[Nn] = Ee;
}

__global__ void k_fill() {
    int e = blockIdx.x * blockDim.x + threadIdx.x;
    if (e >= Ee) return;
    int s = g_src[e];
    int d = g_dst[e];
    int pos = atomicAdd(&g_cursor[d], 1);
    g_nb_src[pos] = s;
    g_nb_nrm[pos] = g_dinv[s] * g_dinv[d];
}

// ---------------- gather aggregation: one warp per node --------------------
// (R15 form verbatim — straight-line 4-edge unroll; manual prefetch regressed)
// MODE 0: out[n] = dinv2*in[n] + sum w*in[s]
// MODE 1: same but every read is relu(bn0(.)); bn params computed inline
// MODE 2: out[n] = dinv2*in[n] + x[n] + b2 + sum w*in[s]
template<int F, int MODE>
__global__ void __launch_bounds__(256)
k_gather(const float* __restrict__ in, const float* __restrict__ xres,
         const float* __restrict__ b2,
         const float* __restrict__ gam, const float* __restrict__ bet,
         float* __restrict__ out) {
    int n = (blockIdx.x * blockDim.x + threadIdx.x) >> 5;
    if (n >= Nn) return;
    int lane = threadIdx.x & 31;
    constexpr int V = F / 128;

    float4 sc[V], sh[V];
    if (MODE == 1) {
#pragma unroll
        for (int v = 0; v < V; v++)
            bn_params4(g_sum0, g_sumsq0, gam, bet, lane + 32 * v, sc[v], sh[v]);
    }
    float di = g_dinv[n], s2 = di * di;
    float4 acc[V];
    {
        const float4* rn = (const float4*)(in + (size_t)n * F);
#pragma unroll
        for (int v = 0; v < V; v++) {
            float4 t = __ldg(&rn[lane + 32 * v]);
            if (MODE == 1) t = bnrelu4(t, sc[v], sh[v]);
            acc[v] = make_float4(t.x * s2, t.y * s2, t.z * s2, t.w * s2);
        }
    }
    if (MODE == 2) {
        const float4* xr = (const float4*)(xres + (size_t)n * F);
#pragma unroll
        for (int v = 0; v < V; v++) {
            float4 xx = __ldg(&xr[lane + 32 * v]);
            float4 bb = __ldg(&((const float4*)b2)[lane + 32 * v]);
            acc[v].x += xx.x + bb.x;
            acc[v].y += xx.y + bb.y;
            acc[v].z += xx.z + bb.z;
            acc[v].w += xx.w + bb.w;
        }
    }

    int e   = g_rowptr[n];
    int end = g_rowptr[n + 1];
    for (; e + 4 <= end; e += 4) {
        int i0 = __ldg(&g_nb_src[e]);
        int i1 = __ldg(&g_nb_src[e + 1]);
        int i2 = __ldg(&g_nb_src[e + 2]);
        int i3 = __ldg(&g_nb_src[e + 3]);
        float w0 = __ldg(&g_nb_nrm[e]);
        float w1 = __ldg(&g_nb_nrm[e + 1]);
        float w2 = __ldg(&g_nb_nrm[e + 2]);
        float w3 = __ldg(&g_nb_nrm[e + 3]);
        const float4* r0 = (const float4*)(in + (size_t)i0 * F) + lane;
        const float4* r1 = (const float4*)(in + (size_t)i1 * F) + lane;
        const float4* r2 = (const float4*)(in + (size_t)i2 * F) + lane;
        const float4* r3 = (const float4*)(in + (size_t)i3 * F) + lane;
#pragma unroll
        for (int v = 0; v < V; v++) {
            float4 t0 = __ldg(r0 + 32 * v);
            float4 t1 = __ldg(r1 + 32 * v);
            float4 t2 = __ldg(r2 + 32 * v);
            float4 t3 = __ldg(r3 + 32 * v);
            if (MODE == 1) {
                t0 = bnrelu4(t0, sc[v], sh[v]);
                t1 = bnrelu4(t1, sc[v], sh[v]);
                t2 = bnrelu4(t2, sc[v], sh[v]);
                t3 = bnrelu4(t3, sc[v], sh[v]);
            }
            fma4(acc[v], t0, w0);
            fma4(acc[v], t1, w1);
            fma4(acc[v], t2, w2);
            fma4(acc[v], t3, w3);
        }
    }
    for (; e < end; e++) {
        int   s = __ldg(&g_nb_src[e]);
        float w = __ldg(&g_nb_nrm[e]);
        const float4* r = (const float4*)(in + (size_t)s * F) + lane;
#pragma unroll
        for (int v = 0; v < V; v++) {
            float4 t = __ldg(r + 32 * v);
            if (MODE == 1) t = bnrelu4(t, sc[v], sh[v]);
            fma4(acc[v], t, w);
        }
    }

    float4* o = (float4*)(out + (size_t)n * F);
#pragma unroll
    for (int v = 0; v < V; v++) __stcs(&o[lane + 32 * v], acc[v]);
}

// ---------------- weight splits: coalesced 32x32 smem-tile transpose --------
// 128 tiles total: W0 (4x8), W1 (8x8), W2 (8x4). Reads and writes coalesced.
__global__ void __launch_bounds__(256)
k_cvtB_t(const float* __restrict__ W0, const float* __restrict__ W1,
         const float* __restrict__ W2) {
    __shared__ float tile[32][33];
    int t = blockIdx.x;
    const float* W; __nv_bfloat16* outp; int K, Nc, kt, nt;
    if (t < 32)      { W = W0; outp = g_W0s; K = DIN; Nc = DH;
                       int l = t;      kt = l & 3; nt = l >> 2; }
    else if (t < 96) { W = W1; outp = g_W1s; K = DH;  Nc = DH;
                       int l = t - 32; kt = l & 7; nt = l >> 3; }
    else             { W = W2; outp = g_W2s; K = DH;  Nc = DOUT;
                       int l = t - 96; kt = l & 7; nt = l >> 3; }
    int tx = threadIdx.x & 31, ty = threadIdx.x >> 5;   // 32 x 8
#pragma unroll
    for (int i = 0; i < 4; i++) {
        int k = kt * 32 + ty + 8 * i;
        tile[ty + 8 * i][tx] = W[(size_t)k * Nc + nt * 32 + tx];
    }
    __syncthreads();
#pragma unroll
    for (int i = 0; i < 4; i++) {
        int n = nt * 32 + ty + 8 * i;
        float v = tile[tx][ty + 8 * i];
        __nv_bfloat16 h = __float2bfloat16(v);
        __nv_bfloat16 l = __float2bfloat16(v - __bfloat162float(h));
        outp[(size_t)n * K + kt * 32 + tx]                    = h;
        outp[(size_t)Nc * K + (size_t)n * K + kt * 32 + tx]   = l;
    }
}

// ---------------- fused-split mma.sync GEMM (40KB static smem, 2 CTAs/SM,
// register double-buffer). FUSE: A = relu(bn1(A)) + relu(bn0(A0)), inline BN.
#define LDPE 40
#define GEMM_PREFETCH(kc)                                                         \
    {                                                                             \
        _Pragma("unroll")                                                         \
        for (int it = 0; it < 4; it++) {                                          \
            int u = tid + it * 256, r = u >> 3, c4 = u & 7;                       \
            int gr = brow + r;                                                    \
            if (gr < Nn) {                                                        \
                pa[it] = *(const float4*)(A + (size_t)gr * K + (kc) + c4 * 4);    \
                if (FUSE)                                                         \
                    pa0[it] = *(const float4*)(A0 + (size_t)gr * K + (kc) + c4 * 4);\
            } else {                                                              \
                pa[it] = make_float4(0.f, 0.f, 0.f, 0.f);                         \
                if (FUSE) pa0[it] = make_float4(0.f, 0.f, 0.f, 0.f);              \
            }                                                                     \
        }                                                                         \
        _Pragma("unroll")                                                         \
        for (int it = 0; it < 2; it++) {                                          \
            int u = tid + it * 256, r = u >> 2, c8 = u & 3;                       \
            const __nv_bfloat16* bp = B2 + (size_t)(bcol + r) * K + (kc) + c8 * 8;\
            pbh[it] = *(const uint4*)bp;                                          \
            pbl[it] = *(const uint4*)(bp + (size_t)NcT * K);                      \
        }                                                                         \
    }

#define GEMM_COMMIT(kc)                                                           \
    {                                                                             \
        float4 s1v, t1v, s0v, t0v;                                                \
        if (FUSE) {                                                               \
            int cb = ((kc) >> 2) + (tid & 7);                                     \
            bn_params4(g_sum1, g_sumsq1, gam1, bet1, cb, s1v, t1v);               \
            bn_params4(g_sum0, g_sumsq0, gam0, bet0, cb, s0v, t0v);               \
        }                                                                         \
        _Pragma("unroll")                                                         \
        for (int it = 0; it < 4; it++) {                                          \
            int u = tid + it * 256, r = u >> 3, c4 = u & 7;                       \
            float4 v4 = pa[it];                                                   \
            if (FUSE) {                                                           \
                v4 = bnrelu4(v4, s1v, t1v);                                       \
                float4 w4 = bnrelu4(pa0[it], s0v, t0v);                           \
                v4.x += w4.x; v4.y += w4.y; v4.z += w4.z; v4.w += w4.w;           \
            }                                                                     \
            float vv[4] = {v4.x, v4.y, v4.z, v4.w};                               \
            __nv_bfloat16 hh[4], ll[4];                                           \
            _Pragma("unroll")                                                     \
            for (int q = 0; q < 4; q++) {                                         \
                hh[q] = __float2bfloat16(vv[q]);                                  \
                ll[q] = __float2bfloat16(vv[q] - __bfloat162float(hh[q]));        \
            }                                                                     \
            *(uint2*)&sAh[r][c4 * 4] = *(uint2*)hh;                               \
            *(uint2*)&sAl[r][c4 * 4] = *(uint2*)ll;                               \
        }                                                                         \
        _Pragma("unroll")                                                         \
        for (int it = 0; it < 2; it++) {                                          \
            int u = tid + it * 256, r = u >> 2, c8 = u & 3;                       \
            *(uint4*)&sBh[r][c8 * 8] = pbh[it];                                   \
            *(uint4*)&sBl[r][c8 * 8] = pbl[it];                                   \
        }                                                                         \
    }

template<int K, bool STATS, bool FUSE>
__global__ void __launch_bounds__(256)
k_gemmF(const float* __restrict__ A, const float* __restrict__ A0,
        const __nv_bfloat16* __restrict__ B2,
        float* __restrict__ C, int NcT,
        float* __restrict__ sumP, float* __restrict__ sumsqP,
        const float* __restrict__ gam0, const float* __restrict__ bet0,
        const float* __restrict__ gam1, const float* __restrict__ bet1) {
    __shared__ __align__(16) __nv_bfloat16 sAh[128][LDPE];
    __shared__ __align__(16) __nv_bfloat16 sAl[128][LDPE];
    __shared__ __align__(16) __nv_bfloat16 sBh[128][LDPE];
    __shared__ __align__(16) __nv_bfloat16 sBl[128][LDPE];

    int tid  = threadIdx.x;
    int wid  = tid >> 5;
    int lane = tid & 31;
    int brow = blockIdx.y * 128;
    int bcol = blockIdx.x * 128;

    int warp_m = wid >> 2;
    int warp_n = wid & 3;
    int m_base = warp_m * 64;
    int n_base = warp_n * 32;

    float acc[4][4][4];
#pragma unroll
    for (int i = 0; i < 4; i++)
#pragma unroll
        for (int j = 0; j < 4; j++)
#pragma unroll
            for (int q = 0; q < 4; q++) acc[i][j][q] = 0.0f;

    float4 pa[4], pa0[4];
    uint4  pbh[2], pbl[2];

    GEMM_PREFETCH(0);
    constexpr int NCH = K / 32;
    for (int c = 0; c < NCH; c++) {
        GEMM_COMMIT(c * 32);
        __syncthreads();
        if (c + 1 < NCH) GEMM_PREFETCH((c + 1) * 32);

#pragma unroll
        for (int ks = 0; ks < 2; ks++) {
            uint32_t ah[4][4], al[4][4];
#pragma unroll
            for (int i = 0; i < 4; i++) {
                int rr = m_base + i * 16 + (lane & 15);
                int cc = ks * 16 + (lane >> 4) * 8;
                uint32_t ad = smem_u32(&sAh[rr][cc]);
                LDSM_X4(ah[i], ad);
                ad = smem_u32(&sAl[rr][cc]);
                LDSM_X4(al[i], ad);
            }
#pragma unroll
            for (int j = 0; j < 4; j++) {
                int rr = n_base + j * 8 + (lane & 7);
                int cc = ks * 16 + ((lane >> 3) & 1) * 8;
                uint32_t bh2[2], bl2[2];
                uint32_t bd = smem_u32(&sBh[rr][cc]);
                LDSM_X2(bh2, bd);
                bd = smem_u32(&sBl[rr][cc]);
                LDSM_X2(bl2, bd);
#pragma unroll
                for (int i = 0; i < 4; i++) {
                    MMA16816(acc[i][j], ah[i], bh2);
                    MMA16816(acc[i][j], al[i], bh2);
                    MMA16816(acc[i][j], ah[i], bl2);
                }
            }
        }
        __syncthreads();
    }

    // write C (streaming: written once, read once later)
#pragma unroll
    for (int i = 0; i < 4; i++) {
        int row0 = brow + m_base + i * 16 + (lane >> 2);
        int row1 = row0 + 8;
#pragma unroll
        for (int j = 0; j < 4; j++) {
            int col = bcol + n_base + j * 8 + (lane & 3) * 2;
            if (row0 < Nn)
                __stcs((float2*)(C + (size_t)row0 * NcT + col),
                       make_float2(acc[i][j][0], acc[i][j][1]));
            if (row1 < Nn)
                __stcs((float2*)(C + (size_t)row1 * NcT + col),
                       make_float2(acc[i][j][2], acc[i][j][3]));
        }
    }

    // fused BN column stats
    if (STATS) {
#pragma unroll
        for (int j = 0; j < 4; j++) {
            float s0 = 0.f, q0 = 0.f, s1 = 0.f, q1 = 0.f;
#pragma unroll
            for (int i = 0; i < 4; i++) {
                int r0 = brow + m_base + i * 16 + (lane >> 2);
                int r1 = r0 + 8;
                float v00 = (r0 < Nn) ? acc[i][j][0] : 0.f;
                float v01 = (r0 < Nn) ? acc[i][j][1] : 0.f;
                float v10 = (r1 < Nn) ? acc[i][j][2] : 0.f;
                float v11 = (r1 < Nn) ? acc[i][j][3] : 0.f;
                s0 += v00 + v10; q0 += v00 * v00 + v10 * v10;
                s1 += v01 + v11; q1 += v01 * v01 + v11 * v11;
            }
#pragma unroll
            for (int m = 4; m <= 16; m <<= 1) {
                s0 += __shfl_xor_sync(0xFFFFFFFFu, s0, m);
                q0 += __shfl_xor_sync(0xFFFFFFFFu, q0, m);
                s1 += __shfl_xor_sync(0xFFFFFFFFu, s1, m);
                q1 += __shfl_xor_sync(0xFFFFFFFFu, q1, m);
            }
            if (lane < 4) {
                int col = bcol + n_base + j * 8 + lane * 2;
                atomicAdd(&sumP[col],       s0);
                atomicAdd(&sumsqP[col],     q0);
                atomicAdd(&sumP[col + 1],   s1);
                atomicAdd(&sumsqP[col + 1], q1);
            }
        }
    }
}

// ---------------- launch ----------------
extern "C" void kernel_launch(void* const* d_in, const int* in_sizes, int n_in,
                              void* d_out, int out_size) {
    const float* x  = (const float*)d_in[0];
    const void*  ei = d_in[1];
    const float* W0 = (const float*)d_in[2];
    // b0 = d_in[3]  (cancels exactly through BatchNorm)
    const float* g0  = (const float*)d_in[4];
    const float* be0 = (const float*)d_in[5];
    const float* W1  = (const float*)d_in[6];
    // b1 = d_in[7]  (cancels exactly through BatchNorm)
    const float* g1  = (const float*)d_in[8];
    const float* be1 = (const float*)d_in[9];
    const float* W2  = (const float*)d_in[10];
    const float* b2  = (const float*)d_in[11];
    float* out = (float*)d_out;

    float *bufA, *bufB, *bufC;
    __nv_bfloat16 *W0s, *W1s, *W2s;
    float *sum0, *sumsq0, *sum1, *sumsq1;
    cudaGetSymbolAddress((void**)&bufA, g_bufA);
    cudaGetSymbolAddress((void**)&bufB, g_bufB);
    cudaGetSymbolAddress((void**)&bufC, g_bufC);
    cudaGetSymbolAddress((void**)&W0s,  g_W0s);
    cudaGetSymbolAddress((void**)&W1s,  g_W1s);
    cudaGetSymbolAddress((void**)&W2s,  g_W2s);
    cudaGetSymbolAddress((void**)&sum0,   g_sum0);
    cudaGetSymbolAddress((void**)&sumsq0, g_sumsq0);
    cudaGetSymbolAddress((void**)&sum1,   g_sum1);
    cudaGetSymbolAddress((void**)&sumsq1, g_sumsq1);

    const int TB = 256;
    int gridE1 = (Ee + TB - 1) / TB;
    int gridN1 = (Nn + TB - 1) / TB;
    int gridW  = (Nn * 32 + TB - 1) / TB;    // 1 warp / node
    dim3 gemmG2(2, NPAD / 128);   // Nc=256
    dim3 gemmG1(1, NPAD / 128);   // Nc=128

    // setup
    k_detect_zero<<<gridN1, TB>>>((const uint2*)ei);
    k_convert<<<gridE1, TB>>>(ei);
    k_scan1  <<<SCANB, 256>>>();
    k_scan3  <<<SCANB, 256>>>();
    k_fill   <<<gridE1, TB>>>();
    k_cvtB_t <<<128, 256>>>(W0, W1, W2);

    // ---- layer 0 ----
    k_gather<DIN, 0><<<gridW, TB>>>(x, nullptr, nullptr, nullptr, nullptr, bufA);
    k_gemmF<DIN, true, false><<<gemmG2, 256>>>(bufA, nullptr, W0s, bufB, DH,
                                               sum0, sumsq0,
                                               nullptr, nullptr, nullptr, nullptr); // H0

    // ---- layer 1: gather applies relu(bn0(.)) with inline BN params ----
    k_gather<DH, 1><<<gridW, TB>>>(bufB, nullptr, nullptr, g0, be0, bufC);
    k_gemmF<DH, true, false><<<gemmG2, 256>>>(bufC, nullptr, W1s, bufA, DH,
                                              sum1, sumsq1,
                                              nullptr, nullptr, nullptr, nullptr);  // M1

    // ---- layer 2: h2 computed in-GEMM from M1(bufA) + H0(bufB), inline BN ----
    k_gemmF<DH, false, true><<<gemmG1, 256>>>(bufA, bufB, W2s, bufC, DOUT,
                                              nullptr, nullptr,
                                              g0, be0, g1, be1);                    // M2
    k_gather<DOUT, 2><<<gridW, TB>>>(bufC, x, b2, nullptr, nullptr, out);
}